// round 13
// baseline (speedup 1.0000x reference)
#include <cuda_runtime.h>
#include <cuda_bf16.h>
#include <math.h>
#include <stdint.h>

// ---------------------------------------------------------------------------
// Problem shapes (fixed)
// ---------------------------------------------------------------------------
#define BATCH 4
#define DIM 192
#define HEADS 8
#define HDIM 24
#define HH 256
#define WW 256
#define HWN 65536
#define QKV_CH 576

#define KEXT 576                     // 3 regions x 192 bf16 slots
#define WROW 288                     // u32 words per extended weight row
#define WCHUNKE (192 * WROW)         // u32 words per 192-row weight chunk

#define GPB 512                      // gram partial blocks per (b,head)
#define CPAIRS 96                    // DIM/2 channel pairs for v

// ---------------------------------------------------------------------------
// Scratch (device globals: allocation-free rule)
// ---------------------------------------------------------------------------
__device__ float g_qkv[(size_t)BATCH * QKV_CH * HWN];
__device__ uint32_t g_vh[(size_t)BATCH * CPAIRS * HWN];   // dwconv(v) hi pairs
__device__ uint32_t g_vl[(size_t)BATCH * CPAIRS * HWN];   // dwconv(v) lo pairs
__device__ float g_spart[(size_t)BATCH * HEADS * GPB * 624];
__device__ float g_attn[BATCH * HEADS * HDIM * HDIM];
__device__ uint32_t g_wext[3 * WCHUNKE];        // qkv weights, 3-term ext rows
__device__ uint32_t g_Mext[BATCH * WCHUNKE];    // proj*blockdiag(attn), ext rows

// ---------------------------------------------------------------------------
// helpers
// ---------------------------------------------------------------------------
__device__ __forceinline__ void split_bf16(float v, uint16_t& h, uint16_t& l) {
    __nv_bfloat16 bh = __float2bfloat16(v);
    float r = v - __bfloat162float(bh);
    __nv_bfloat16 bl = __float2bfloat16(r);
    h = __bfloat16_as_ushort(bh);
    l = __bfloat16_as_ushort(bl);
}

__device__ __forceinline__ void mma16816(float* c, const uint32_t* a, const uint32_t* b) {
    asm volatile(
        "mma.sync.aligned.m16n8k16.row.col.f32.bf16.bf16.f32 "
        "{%0,%1,%2,%3}, {%4,%5,%6,%7}, {%8,%9}, {%0,%1,%2,%3};"
        : "+f"(c[0]), "+f"(c[1]), "+f"(c[2]), "+f"(c[3])
        : "r"(a[0]), "r"(a[1]), "r"(a[2]), "r"(a[3]), "r"(b[0]), "r"(b[1]));
}

// ---------------------------------------------------------------------------
// K0: split qkv weights -> extended bf16 rows [576 rows][576 slots]
// slot k = hi, 192+k = lo, 384+k = hi
// ---------------------------------------------------------------------------
__global__ __launch_bounds__(256)
void wprep_k(const float* __restrict__ w, uint32_t* __restrict__ wext)
{
    int idx = blockIdx.x * 256 + threadIdx.x;
    if (idx >= QKV_CH * DIM) return;
    int r = idx / DIM, k = idx % DIM;
    uint16_t h, l;
    split_bf16(w[idx], h, l);
    uint16_t* row = (uint16_t*)wext + (size_t)r * KEXT;
    row[k] = h;
    row[192 + k] = l;
    row[384 + k] = h;
}

// ---------------------------------------------------------------------------
// tgemm (R6-frozen body, templated chunk count; R11-proven):
// C[m][px] = sum_c W[m][c]*src[c][px], 3-term bf16 split, mma.sync.
// ---------------------------------------------------------------------------
#define AS_STR 20
#define BS_STR 100
#define TGEMM_SMEM ((192 * AS_STR + 2 * 128 * BS_STR) * 4)   // 117760 B

template <int NCHUNK>
__global__ __launch_bounds__(512, 1)
void tgemm_k(const uint32_t* __restrict__ wext, const float* __restrict__ src,
             float* __restrict__ out, size_t wBS, size_t srcBS, size_t outBS)
{
    extern __shared__ uint32_t dsm[];
    uint32_t* As   = dsm;                        // [192][AS_STR]
    uint32_t* Bs_h = dsm + 192 * AS_STR;         // [128 px][BS_STR] (96 used)
    uint32_t* Bs_l = Bs_h + 128 * BS_STR;

    const int tid = threadIdx.x;
    const int wid = tid >> 5;
    const int lane = tid & 31;
    const int g = lane >> 2;
    const int tig = lane & 3;
    const int warpM = wid & 3;
    const int warpN = wid >> 2;

    const int p0 = blockIdx.x * 128;
    const int b = blockIdx.y;

    const uint32_t* wp0 = wext + (size_t)b * wBS;
    const float* sp = src + (size_t)b * srcBS + p0;

    // ---- phase 1: convert pixel tile -> resident Bs_h / Bs_l (once)
#pragma unroll
    for (int pass = 0; pass < 6; pass++) {
        int cpair = pass * 16 + wid;
        const float* r0 = sp + ((size_t)(2 * cpair) << 16);
        const float* r1 = sp + ((size_t)(2 * cpair + 1) << 16);
#pragma unroll
        for (int i = 0; i < 4; i++) {
            int px = lane + 32 * i;
            uint16_t h0, l0, h1, l1;
            split_bf16(__ldg(r0 + px), h0, l0);
            split_bf16(__ldg(r1 + px), h1, l1);
            Bs_h[px * BS_STR + cpair] = (uint32_t)h1 << 16 | h0;
            Bs_l[px * BS_STR + cpair] = (uint32_t)l1 << 16 | l0;
        }
    }

    // A slab loader indices (192 rows x 16 u32 per slab)
    const int aM0 = tid >> 2;
    const int aM1 = 128 + (tid >> 2);
    const int aJ = (tid & 3) * 4;

    for (int chunk = 0; chunk < NCHUNK; chunk++) {
        const uint32_t* wp = wp0 + (size_t)chunk * WCHUNKE;

        float acc[3][4][4];
#pragma unroll
        for (int mt = 0; mt < 3; mt++)
#pragma unroll
            for (int nt = 0; nt < 4; nt++)
#pragma unroll
                for (int i = 0; i < 4; i++) acc[mt][nt][i] = 0.f;

        uint4 apf0, apf1;
        apf0 = *(const uint4*)(wp + (size_t)aM0 * WROW + aJ);
        if (tid < 256) apf1 = *(const uint4*)(wp + (size_t)aM1 * WROW + aJ);
        __syncthreads();   // Bs ready / prior chunk fully done

        for (int it = 0; it < 18; it++) {
            *(uint4*)&As[aM0 * AS_STR + aJ] = apf0;
            if (tid < 256) *(uint4*)&As[aM1 * AS_STR + aJ] = apf1;
            __syncthreads();

            if (it < 17) {
                const uint32_t* wpn = wp + (it + 1) * 16;
                apf0 = *(const uint4*)(wpn + (size_t)aM0 * WROW + aJ);
                if (tid < 256) apf1 = *(const uint4*)(wpn + (size_t)aM1 * WROW + aJ);
            }

            const uint32_t* BsR = (it < 12) ? Bs_h : Bs_l;
            const int bbase = (it % 6) * 16;

#pragma unroll
            for (int ks = 0; ks < 2; ks++) {
                const int kc = ks * 8;
                uint32_t afr[3][4], bfr[4][2];
#pragma unroll
                for (int mt = 0; mt < 3; mt++) {
                    int r0 = warpM * 48 + mt * 16 + g;
                    afr[mt][0] = As[r0 * AS_STR + kc + tig];
                    afr[mt][1] = As[(r0 + 8) * AS_STR + kc + tig];
                    afr[mt][2] = As[r0 * AS_STR + kc + 4 + tig];
                    afr[mt][3] = As[(r0 + 8) * AS_STR + kc + 4 + tig];
                }
#pragma unroll
                for (int nt = 0; nt < 4; nt++) {
                    int n = warpN * 32 + nt * 8 + g;
                    bfr[nt][0] = BsR[n * BS_STR + bbase + kc + tig];
                    bfr[nt][1] = BsR[n * BS_STR + bbase + kc + 4 + tig];
                }
#pragma unroll
                for (int mt = 0; mt < 3; mt++)
#pragma unroll
                    for (int nt = 0; nt < 4; nt++)
                        mma16816(acc[mt][nt], afr[mt], bfr[nt]);
            }
            __syncthreads();
        }

        float* op = out + (size_t)b * outBS + ((size_t)chunk * 192 << 16);
#pragma unroll
        for (int mt = 0; mt < 3; mt++) {
#pragma unroll
            for (int nt = 0; nt < 4; nt++) {
                int row = warpM * 48 + mt * 16 + g;
                int col = p0 + warpN * 32 + nt * 8 + tig * 2;
                *(float2*)&op[((size_t)row << 16) + col] =
                    make_float2(acc[mt][nt][0], acc[mt][nt][1]);
                *(float2*)&op[((size_t)(row + 8) << 16) + col] =
                    make_float2(acc[mt][nt][2], acc[mt][nt][3]);
            }
        }
    }
}

// ---------------------------------------------------------------------------
// K7: out = M @ V where V is pre-split (g_vh/g_vl).  Frozen mainloop verbatim;
// phase-1 is a pure coalesced u32 copy (zero conversion ALU).
// ---------------------------------------------------------------------------
__global__ __launch_bounds__(512, 1)
void tgemmp_k(const uint32_t* __restrict__ wext, const uint32_t* __restrict__ vh,
              const uint32_t* __restrict__ vl, float* __restrict__ out)
{
    extern __shared__ uint32_t dsm[];
    uint32_t* As   = dsm;                        // [192][AS_STR]
    uint32_t* Bs_h = dsm + 192 * AS_STR;         // [128 px][BS_STR] (96 used)
    uint32_t* Bs_l = Bs_h + 128 * BS_STR;

    const int tid = threadIdx.x;
    const int wid = tid >> 5;
    const int lane = tid & 31;
    const int g = lane >> 2;
    const int tig = lane & 3;
    const int warpM = wid & 3;
    const int warpN = wid >> 2;

    const int p0 = blockIdx.x * 128;
    const int b = blockIdx.y;

    const uint32_t* wp0 = wext + (size_t)b * WCHUNKE;

    // ---- phase 1: load pre-split pixel tile -> resident Bs_h / Bs_l
#pragma unroll
    for (int pass = 0; pass < 6; pass++) {
        int cpair = pass * 16 + wid;
        const uint32_t* gh = vh + (((size_t)(b * CPAIRS + cpair)) << 16) + p0;
        const uint32_t* gl = vl + (((size_t)(b * CPAIRS + cpair)) << 16) + p0;
#pragma unroll
        for (int i = 0; i < 4; i++) {
            int px = lane + 32 * i;
            Bs_h[px * BS_STR + cpair] = __ldg(gh + px);
            Bs_l[px * BS_STR + cpair] = __ldg(gl + px);
        }
    }

    // ---- from here: byte-identical frozen mainloop (single chunk)
    const int aM0 = tid >> 2;
    const int aM1 = 128 + (tid >> 2);
    const int aJ = (tid & 3) * 4;

    {
        const uint32_t* wp = wp0;

        float acc[3][4][4];
#pragma unroll
        for (int mt = 0; mt < 3; mt++)
#pragma unroll
            for (int nt = 0; nt < 4; nt++)
#pragma unroll
                for (int i = 0; i < 4; i++) acc[mt][nt][i] = 0.f;

        uint4 apf0, apf1;
        apf0 = *(const uint4*)(wp + (size_t)aM0 * WROW + aJ);
        if (tid < 256) apf1 = *(const uint4*)(wp + (size_t)aM1 * WROW + aJ);
        __syncthreads();   // Bs ready

        for (int it = 0; it < 18; it++) {
            *(uint4*)&As[aM0 * AS_STR + aJ] = apf0;
            if (tid < 256) *(uint4*)&As[aM1 * AS_STR + aJ] = apf1;
            __syncthreads();

            if (it < 17) {
                const uint32_t* wpn = wp + (it + 1) * 16;
                apf0 = *(const uint4*)(wpn + (size_t)aM0 * WROW + aJ);
                if (tid < 256) apf1 = *(const uint4*)(wpn + (size_t)aM1 * WROW + aJ);
            }

            const uint32_t* BsR = (it < 12) ? Bs_h : Bs_l;
            const int bbase = (it % 6) * 16;

#pragma unroll
            for (int ks = 0; ks < 2; ks++) {
                const int kc = ks * 8;
                uint32_t afr[3][4], bfr[4][2];
#pragma unroll
                for (int mt = 0; mt < 3; mt++) {
                    int r0 = warpM * 48 + mt * 16 + g;
                    afr[mt][0] = As[r0 * AS_STR + kc + tig];
                    afr[mt][1] = As[(r0 + 8) * AS_STR + kc + tig];
                    afr[mt][2] = As[r0 * AS_STR + kc + 4 + tig];
                    afr[mt][3] = As[(r0 + 8) * AS_STR + kc + 4 + tig];
                }
#pragma unroll
                for (int nt = 0; nt < 4; nt++) {
                    int n = warpN * 32 + nt * 8 + g;
                    bfr[nt][0] = BsR[n * BS_STR + bbase + kc + tig];
                    bfr[nt][1] = BsR[n * BS_STR + bbase + kc + 4 + tig];
                }
#pragma unroll
                for (int mt = 0; mt < 3; mt++)
#pragma unroll
                    for (int nt = 0; nt < 4; nt++)
                        mma16816(acc[mt][nt], afr[mt], bfr[nt]);
            }
            __syncthreads();
        }

        float* op = out + (size_t)b * DIM * HWN;
#pragma unroll
        for (int mt = 0; mt < 3; mt++) {
#pragma unroll
            for (int nt = 0; nt < 4; nt++) {
                int row = warpM * 48 + mt * 16 + g;
                int col = p0 + warpN * 32 + nt * 8 + tig * 2;
                *(float2*)&op[((size_t)row << 16) + col] =
                    make_float2(acc[mt][nt][0], acc[mt][nt][1]);
                *(float2*)&op[((size_t)(row + 8) << 16) + col] =
                    make_float2(acc[mt][nt][2], acc[mt][nt][3]);
            }
        }
    }
}

// ---------------------------------------------------------------------------
// K2: fused dwconv (q,k) + Gram partials + norms — R6-proven.
// ---------------------------------------------------------------------------
__global__ __launch_bounds__(192)
void dwgram_k(const float* __restrict__ qkv, const float* __restrict__ dww,
              float* __restrict__ spart)
{
    __shared__ float qs[24][132];
    __shared__ float ks[24][132];

    const int b = blockIdx.z, h = blockIdx.y;
    const int y = blockIdx.x >> 1;
    const int x0 = (blockIdx.x & 1) * 128;
    const int tid = threadIdx.x;

    for (int u = tid; u < 48 * 32; u += 192) {
        int c = u >> 5;
        int xu = u & 31;
        int xg = x0 + xu * 4;
        int ch = (c < 24) ? (h * 24 + c) : (192 + h * 24 + (c - 24));
        const float* in = qkv + ((size_t)(b * QKV_CH + ch) << 16);
        const float* w9 = dww + ch * 9;
        float a0 = 0.f, a1 = 0.f, a2 = 0.f, a3 = 0.f;
#pragma unroll
        for (int dy = -1; dy <= 1; dy++) {
            int yy = y + dy;
            if (yy < 0 || yy > HH - 1) continue;
            const float* r = in + yy * WW;
            float4 m = *(const float4*)(r + xg);
            float left  = (xg > 0)      ? __ldg(r + xg - 1) : 0.f;
            float right = (xg < WW - 4) ? __ldg(r + xg + 4) : 0.f;
            float w0 = __ldg(w9 + (dy + 1) * 3 + 0);
            float w1 = __ldg(w9 + (dy + 1) * 3 + 1);
            float w2 = __ldg(w9 + (dy + 1) * 3 + 2);
            a0 = fmaf(w0, left, fmaf(w1, m.x, fmaf(w2, m.y, a0)));
            a1 = fmaf(w0, m.x,  fmaf(w1, m.y, fmaf(w2, m.z, a1)));
            a2 = fmaf(w0, m.y,  fmaf(w1, m.z, fmaf(w2, m.w, a2)));
            a3 = fmaf(w0, m.z,  fmaf(w1, m.w, fmaf(w2, right, a3)));
        }
        float* dst = (c < 24) ? &qs[c][xu * 4] : &ks[c - 24][xu * 4];
        *(float4*)dst = make_float4(a0, a1, a2, a3);
    }
    __syncthreads();

    float* out = spart + ((size_t)(b * HEADS + h) * GPB + blockIdx.x) * 624;

    if (tid < 144) {
        int d = (tid / 12) * 2, e = (tid % 12) * 2;
        float a00 = 0, a01 = 0, a10 = 0, a11 = 0;
#pragma unroll 4
        for (int n = 0; n < 128; n += 4) {
            float4 q0 = *(const float4*)&qs[d][n];
            float4 q1 = *(const float4*)&qs[d + 1][n];
            float4 k0 = *(const float4*)&ks[e][n];
            float4 k1 = *(const float4*)&ks[e + 1][n];
            a00 = fmaf(q0.x, k0.x, fmaf(q0.y, k0.y, fmaf(q0.z, k0.z, fmaf(q0.w, k0.w, a00))));
            a01 = fmaf(q0.x, k1.x, fmaf(q0.y, k1.y, fmaf(q0.z, k1.z, fmaf(q0.w, k1.w, a01))));
            a10 = fmaf(q1.x, k0.x, fmaf(q1.y, k0.y, fmaf(q1.z, k0.z, fmaf(q1.w, k0.w, a10))));
            a11 = fmaf(q1.x, k1.x, fmaf(q1.y, k1.y, fmaf(q1.z, k1.z, fmaf(q1.w, k1.w, a11))));
        }
        out[d * 24 + e] = a00;
        out[d * 24 + e + 1] = a01;
        out[(d + 1) * 24 + e] = a10;
        out[(d + 1) * 24 + e + 1] = a11;
    } else if (tid < 168) {
        int d = tid - 144;
        float s = 0;
#pragma unroll 4
        for (int n = 0; n < 128; n += 4) {
            float4 q = *(const float4*)&qs[d][n];
            s = fmaf(q.x, q.x, fmaf(q.y, q.y, fmaf(q.z, q.z, fmaf(q.w, q.w, s))));
        }
        out[576 + d] = s;
    } else {
        int e = tid - 168;
        float s = 0;
#pragma unroll 4
        for (int n = 0; n < 128; n += 4) {
            float4 q = *(const float4*)&ks[e][n];
            s = fmaf(q.x, q.x, fmaf(q.y, q.y, fmaf(q.z, q.z, fmaf(q.w, q.w, s))));
        }
        out[600 + e] = s;
    }
}

// ---------------------------------------------------------------------------
// K3: dwconv for v channel PAIRS — 4 px/thread, writes pre-split hi/lo pairs.
// Grid (HH/4, CPAIRS, BATCH), block 256: y = bx*4 + tid/64, x0 = (tid%64)*4.
// Conv math bit-identical to the proven dwv_k; split applied to the result.
// ---------------------------------------------------------------------------
__global__ __launch_bounds__(256)
void dwv2_k(const float* __restrict__ qkv, const float* __restrict__ dww,
            uint32_t* __restrict__ vh, uint32_t* __restrict__ vl)
{
    const int b = blockIdx.z, cp = blockIdx.y;
    const int tid = threadIdx.x;
    const int y = blockIdx.x * 4 + (tid >> 6);
    const int x0 = (tid & 63) * 4;
    const int ch0 = 384 + 2 * cp;
    const float* in0 = qkv + ((size_t)(b * QKV_CH + ch0) << 16);
    const float* in1 = in0 + HWN;

    float wA[9], wB[9];
#pragma unroll
    for (int i = 0; i < 9; i++) {
        wA[i] = __ldg(dww + ch0 * 9 + i);
        wB[i] = __ldg(dww + (ch0 + 1) * 9 + i);
    }

    float a0 = 0.f, a1 = 0.f, a2 = 0.f, a3 = 0.f;
    float b0 = 0.f, b1 = 0.f, b2 = 0.f, b3 = 0.f;
#pragma unroll
    for (int dy = -1; dy <= 1; dy++) {
        int yy = y + dy;
        if (yy < 0 || yy > HH - 1) continue;
        {
            const float* r = in0 + yy * WW;
            float4 m = *(const float4*)(r + x0);
            float left  = (x0 > 0)      ? __ldg(r + x0 - 1) : 0.f;
            float right = (x0 < WW - 4) ? __ldg(r + x0 + 4) : 0.f;
            const float w0 = wA[(dy + 1) * 3 + 0];
            const float w1 = wA[(dy + 1) * 3 + 1];
            const float w2 = wA[(dy + 1) * 3 + 2];
            a0 = fmaf(w0, left, fmaf(w1, m.x, fmaf(w2, m.y, a0)));
            a1 = fmaf(w0, m.x,  fmaf(w1, m.y, fmaf(w2, m.z, a1)));
            a2 = fmaf(w0, m.y,  fmaf(w1, m.z, fmaf(w2, m.w, a2)));
            a3 = fmaf(w0, m.z,  fmaf(w1, m.w, fmaf(w2, right, a3)));
        }
        {
            const float* r = in1 + yy * WW;
            float4 m = *(const float4*)(r + x0);
            float left  = (x0 > 0)      ? __ldg(r + x0 - 1) : 0.f;
            float right = (x0 < WW - 4) ? __ldg(r + x0 + 4) : 0.f;
            const float w0 = wB[(dy + 1) * 3 + 0];
            const float w1 = wB[(dy + 1) * 3 + 1];
            const float w2 = wB[(dy + 1) * 3 + 2];
            b0 = fmaf(w0, left, fmaf(w1, m.x, fmaf(w2, m.y, b0)));
            b1 = fmaf(w0, m.x,  fmaf(w1, m.y, fmaf(w2, m.z, b1)));
            b2 = fmaf(w0, m.y,  fmaf(w1, m.z, fmaf(w2, m.w, b2)));
            b3 = fmaf(w0, m.z,  fmaf(w1, m.w, fmaf(w2, right, b3)));
        }
    }

    uint16_t h, l, h2, l2;
    uint4 oh, ol;
    split_bf16(a0, h, l); split_bf16(b0, h2, l2);
    oh.x = (uint32_t)h2 << 16 | h; ol.x = (uint32_t)l2 << 16 | l;
    split_bf16(a1, h, l); split_bf16(b1, h2, l2);
    oh.y = (uint32_t)h2 << 16 | h; ol.y = (uint32_t)l2 << 16 | l;
    split_bf16(a2, h, l); split_bf16(b2, h2, l2);
    oh.z = (uint32_t)h2 << 16 | h; ol.z = (uint32_t)l2 << 16 | l;
    split_bf16(a3, h, l); split_bf16(b3, h2, l2);
    oh.w = (uint32_t)h2 << 16 | h; ol.w = (uint32_t)l2 << 16 | l;

    size_t off = ((size_t)(b * CPAIRS + cp) << 16) + y * WW + x0;
    *(uint4*)&vh[off] = oh;
    *(uint4*)&vl[off] = ol;
}

// ---------------------------------------------------------------------------
// K4+K5 fused: reduce GPB Gram partials, then softmax. Grid 32, block 624.
// ---------------------------------------------------------------------------
__global__ __launch_bounds__(624)
void redsoft_k(const float* __restrict__ spart, const float* __restrict__ temp,
               float* __restrict__ attn)
{
    const int bh = blockIdx.x;
    const int h = bh & 7;
    const int j = threadIdx.x;

    __shared__ float S[624];
    __shared__ float lg[24][24];
    __shared__ float rmax[24], rsum[24];

    {
        const float* p = spart + (size_t)bh * GPB * 624 + j;
        float s = 0.f;
        for (int y = 0; y < GPB; y++) s += p[(size_t)y * 624];
        S[j] = s;
    }
    __syncthreads();

    const int d = j / 24, e = j % 24;
    float l = 0.f;
    if (j < 576) {
        float nq = fmaxf(sqrtf(S[576 + d]), 1e-12f);
        float nk = fmaxf(sqrtf(S[600 + e]), 1e-12f);
        l = S[d * 24 + e] / (nq * nk) * temp[h];
        lg[d][e] = l;
    }
    __syncthreads();
    if (j < 576 && e == 0) {
        float m = -1e30f;
        for (int t = 0; t < 24; t++) m = fmaxf(m, lg[d][t]);
        rmax[d] = m;
    }
    __syncthreads();
    float ex = 0.f;
    if (j < 576) {
        ex = expf(l - rmax[d]);
        lg[d][e] = ex;
    }
    __syncthreads();
    if (j < 576 && e == 0) {
        float s = 0.f;
        for (int t = 0; t < 24; t++) s += lg[d][t];
        rsum[d] = s;
    }
    __syncthreads();
    if (j < 576) attn[bh * 576 + d * 24 + e] = ex / rsum[d];
}

// ---------------------------------------------------------------------------
// K6: M[b] = P * blockdiag(attn[b]) -> extended bf16 rows
// ---------------------------------------------------------------------------
__global__ __launch_bounds__(256)
void buildM_k(const float* __restrict__ attn, const float* __restrict__ P,
              uint32_t* __restrict__ Mext)
{
    const int b = blockIdx.x;
    __shared__ float at[HEADS * 576];
    for (int i = threadIdx.x; i < HEADS * 576; i += 256) at[i] = attn[b * HEADS * 576 + i];
    __syncthreads();

    for (int idx = threadIdx.x; idx < DIM * DIM; idx += 256) {
        int o = idx / DIM, c = idx % DIM;
        int hh = c / 24, e = c % 24;
        float s = 0.f;
#pragma unroll
        for (int d = 0; d < 24; d++)
            s = fmaf(P[o * DIM + hh * 24 + d], at[hh * 576 + d * 24 + e], s);
        uint16_t h, l;
        split_bf16(s, h, l);
        uint16_t* row = (uint16_t*)(Mext + (size_t)b * WCHUNKE) + (size_t)o * KEXT;
        row[c] = h;
        row[192 + c] = l;
        row[384 + c] = h;
    }
}

// ---------------------------------------------------------------------------
// launch
// ---------------------------------------------------------------------------
extern "C" void kernel_launch(void* const* d_in, const int* in_sizes, int n_in,
                              void* d_out, int out_size)
{
    const float* x      = (const float*)d_in[0];
    const float* qkv_w  = (const float*)d_in[1];
    const float* dw_w   = (const float*)d_in[2];
    const float* proj_w = (const float*)d_in[3];
    const float* temp   = (const float*)d_in[4];
    float* out = (float*)d_out;

    float *qkv_s, *spart, *attn;
    uint32_t *wext, *Mext, *vh, *vl;
    cudaGetSymbolAddress((void**)&qkv_s, g_qkv);
    cudaGetSymbolAddress((void**)&spart, g_spart);
    cudaGetSymbolAddress((void**)&attn,  g_attn);
    cudaGetSymbolAddress((void**)&wext,  g_wext);
    cudaGetSymbolAddress((void**)&Mext,  g_Mext);
    cudaGetSymbolAddress((void**)&vh,    g_vh);
    cudaGetSymbolAddress((void**)&vl,    g_vl);

    cudaFuncSetAttribute(tgemm_k<3>, cudaFuncAttributeMaxDynamicSharedMemorySize,
                         TGEMM_SMEM);
    cudaFuncSetAttribute(tgemmp_k, cudaFuncAttributeMaxDynamicSharedMemorySize,
                         TGEMM_SMEM);

    // K0: weight split/extend
    wprep_k<<<(QKV_CH * DIM + 255) / 256, 256>>>(qkv_w, wext);

    // K1: qkv = W_qkv @ x  (3 m-chunks internal; B tile converted once)
    {
        dim3 grid(HWN / 128, BATCH);
        tgemm_k<3><<<grid, 512, TGEMM_SMEM>>>(wext, x, qkv_s, 0,
                                              (size_t)DIM * HWN, (size_t)QKV_CH * HWN);
    }
    // K2: fused dwconv(q,k) + Gram partials
    {
        dim3 grid(GPB, HEADS, BATCH);
        dwgram_k<<<grid, 192>>>(qkv_s, dw_w, spart);
    }
    // K3: dwconv(v) channel pairs -> pre-split hi/lo
    {
        dim3 grid(HH / 4, CPAIRS, BATCH);
        dwv2_k<<<grid, 256>>>(qkv_s, dw_w, vh, vl);
    }
    // K4+K5 fused: reduce + softmax
    redsoft_k<<<BATCH * HEADS, 624>>>(spart, temp, attn);
    // K6: M = P * blockdiag(attn) -> extended bf16
    buildM_k<<<BATCH, 256>>>(attn, proj_w, Mext);
    // K7: out = M @ V  (pre-split B; zero-conversion phase-1)
    {
        dim3 grid(HWN / 128, BATCH);
        tgemmp_k<<<grid, 512, TGEMM_SMEM>>>(Mext, vh, vl, out);
    }
}

// round 14
// speedup vs baseline: 1.4805x; 1.4805x over previous
#include <cuda_runtime.h>
#include <cuda_bf16.h>
#include <math.h>
#include <stdint.h>

// ---------------------------------------------------------------------------
// Problem shapes (fixed)
// ---------------------------------------------------------------------------
#define BATCH 4
#define DIM 192
#define HEADS 8
#define HDIM 24
#define HH 256
#define WW 256
#define HWN 65536
#define QKV_CH 576

#define KEXT 576                     // 3 regions x 192 bf16 slots
#define WROW 288                     // u32 words per extended weight row
#define WCHUNKE (192 * WROW)         // u32 words per 192-row weight chunk

#define GPB 512                      // gram partial blocks per (b,head)

// ---------------------------------------------------------------------------
// Scratch (device globals: allocation-free rule)
// ---------------------------------------------------------------------------
__device__ float g_qkv[(size_t)BATCH * QKV_CH * HWN];
__device__ float g_v[(size_t)BATCH * DIM * HWN];
__device__ float g_spart[(size_t)BATCH * HEADS * GPB * 624];
__device__ float g_attn[BATCH * HEADS * HDIM * HDIM];
__device__ uint32_t g_wext[3 * WCHUNKE];        // qkv weights, 3-term ext rows
__device__ uint32_t g_Mext[BATCH * WCHUNKE];    // proj*blockdiag(attn), ext rows

// ---------------------------------------------------------------------------
// helpers
// ---------------------------------------------------------------------------
__device__ __forceinline__ void split_bf16(float v, uint16_t& h, uint16_t& l) {
    __nv_bfloat16 bh = __float2bfloat16(v);
    float r = v - __bfloat162float(bh);
    __nv_bfloat16 bl = __float2bfloat16(r);
    h = __bfloat16_as_ushort(bh);
    l = __bfloat16_as_ushort(bl);
}

__device__ __forceinline__ void mma16816(float* c, const uint32_t* a, const uint32_t* b) {
    asm volatile(
        "mma.sync.aligned.m16n8k16.row.col.f32.bf16.bf16.f32 "
        "{%0,%1,%2,%3}, {%4,%5,%6,%7}, {%8,%9}, {%0,%1,%2,%3};"
        : "+f"(c[0]), "+f"(c[1]), "+f"(c[2]), "+f"(c[3])
        : "r"(a[0]), "r"(a[1]), "r"(a[2]), "r"(a[3]), "r"(b[0]), "r"(b[1]));
}

// ---------------------------------------------------------------------------
// K0: split qkv weights -> extended bf16 rows [576 rows][576 slots]
// slot k = hi, 192+k = lo, 384+k = hi
// ---------------------------------------------------------------------------
__global__ __launch_bounds__(256)
void wprep_k(const float* __restrict__ w, uint32_t* __restrict__ wext)
{
    int idx = blockIdx.x * 256 + threadIdx.x;
    if (idx >= QKV_CH * DIM) return;
    int r = idx / DIM, k = idx % DIM;
    uint16_t h, l;
    split_bf16(w[idx], h, l);
    uint16_t* row = (uint16_t*)wext + (size_t)r * KEXT;
    row[k] = h;
    row[192 + k] = l;
    row[384 + k] = h;
}

// ---------------------------------------------------------------------------
// tgemm (R6-frozen body, templated chunk count; R11-proven — IMMUTABLE):
// C[m][px] = sum_c W[m][c]*src[c][px], 3-term bf16 split, mma.sync.
// ---------------------------------------------------------------------------
#define AS_STR 20
#define BS_STR 100
#define TGEMM_SMEM ((192 * AS_STR + 2 * 128 * BS_STR) * 4)   // 117760 B

template <int NCHUNK>
__global__ __launch_bounds__(512, 1)
void tgemm_k(const uint32_t* __restrict__ wext, const float* __restrict__ src,
             float* __restrict__ out, size_t wBS, size_t srcBS, size_t outBS)
{
    extern __shared__ uint32_t dsm[];
    uint32_t* As   = dsm;                        // [192][AS_STR]
    uint32_t* Bs_h = dsm + 192 * AS_STR;         // [128 px][BS_STR] (96 used)
    uint32_t* Bs_l = Bs_h + 128 * BS_STR;

    const int tid = threadIdx.x;
    const int wid = tid >> 5;
    const int lane = tid & 31;
    const int g = lane >> 2;
    const int tig = lane & 3;
    const int warpM = wid & 3;
    const int warpN = wid >> 2;

    const int p0 = blockIdx.x * 128;
    const int b = blockIdx.y;

    const uint32_t* wp0 = wext + (size_t)b * wBS;
    const float* sp = src + (size_t)b * srcBS + p0;

    // ---- phase 1: convert pixel tile -> resident Bs_h / Bs_l (once)
#pragma unroll
    for (int pass = 0; pass < 6; pass++) {
        int cpair = pass * 16 + wid;
        const float* r0 = sp + ((size_t)(2 * cpair) << 16);
        const float* r1 = sp + ((size_t)(2 * cpair + 1) << 16);
#pragma unroll
        for (int i = 0; i < 4; i++) {
            int px = lane + 32 * i;
            uint16_t h0, l0, h1, l1;
            split_bf16(__ldg(r0 + px), h0, l0);
            split_bf16(__ldg(r1 + px), h1, l1);
            Bs_h[px * BS_STR + cpair] = (uint32_t)h1 << 16 | h0;
            Bs_l[px * BS_STR + cpair] = (uint32_t)l1 << 16 | l0;
        }
    }

    // A slab loader indices (192 rows x 16 u32 per slab)
    const int aM0 = tid >> 2;
    const int aM1 = 128 + (tid >> 2);
    const int aJ = (tid & 3) * 4;

    for (int chunk = 0; chunk < NCHUNK; chunk++) {
        const uint32_t* wp = wp0 + (size_t)chunk * WCHUNKE;

        float acc[3][4][4];
#pragma unroll
        for (int mt = 0; mt < 3; mt++)
#pragma unroll
            for (int nt = 0; nt < 4; nt++)
#pragma unroll
                for (int i = 0; i < 4; i++) acc[mt][nt][i] = 0.f;

        uint4 apf0, apf1;
        apf0 = *(const uint4*)(wp + (size_t)aM0 * WROW + aJ);
        if (tid < 256) apf1 = *(const uint4*)(wp + (size_t)aM1 * WROW + aJ);
        __syncthreads();   // Bs ready / prior chunk fully done

        for (int it = 0; it < 18; it++) {
            *(uint4*)&As[aM0 * AS_STR + aJ] = apf0;
            if (tid < 256) *(uint4*)&As[aM1 * AS_STR + aJ] = apf1;
            __syncthreads();

            if (it < 17) {
                const uint32_t* wpn = wp + (it + 1) * 16;
                apf0 = *(const uint4*)(wpn + (size_t)aM0 * WROW + aJ);
                if (tid < 256) apf1 = *(const uint4*)(wpn + (size_t)aM1 * WROW + aJ);
            }

            const uint32_t* BsR = (it < 12) ? Bs_h : Bs_l;
            const int bbase = (it % 6) * 16;

#pragma unroll
            for (int ks = 0; ks < 2; ks++) {
                const int kc = ks * 8;
                uint32_t afr[3][4], bfr[4][2];
#pragma unroll
                for (int mt = 0; mt < 3; mt++) {
                    int r0 = warpM * 48 + mt * 16 + g;
                    afr[mt][0] = As[r0 * AS_STR + kc + tig];
                    afr[mt][1] = As[(r0 + 8) * AS_STR + kc + tig];
                    afr[mt][2] = As[r0 * AS_STR + kc + 4 + tig];
                    afr[mt][3] = As[(r0 + 8) * AS_STR + kc + 4 + tig];
                }
#pragma unroll
                for (int nt = 0; nt < 4; nt++) {
                    int n = warpN * 32 + nt * 8 + g;
                    bfr[nt][0] = BsR[n * BS_STR + bbase + kc + tig];
                    bfr[nt][1] = BsR[n * BS_STR + bbase + kc + 4 + tig];
                }
#pragma unroll
                for (int mt = 0; mt < 3; mt++)
#pragma unroll
                    for (int nt = 0; nt < 4; nt++)
                        mma16816(acc[mt][nt], afr[mt], bfr[nt]);
            }
            __syncthreads();
        }

        float* op = out + (size_t)b * outBS + ((size_t)chunk * 192 << 16);
#pragma unroll
        for (int mt = 0; mt < 3; mt++) {
#pragma unroll
            for (int nt = 0; nt < 4; nt++) {
                int row = warpM * 48 + mt * 16 + g;
                int col = p0 + warpN * 32 + nt * 8 + tig * 2;
                *(float2*)&op[((size_t)row << 16) + col] =
                    make_float2(acc[mt][nt][0], acc[mt][nt][1]);
                *(float2*)&op[((size_t)(row + 8) << 16) + col] =
                    make_float2(acc[mt][nt][2], acc[mt][nt][3]);
            }
        }
    }
}

// ---------------------------------------------------------------------------
// K2: fused dwconv (q,k) + Gram partials + norms — halo via warp shuffle.
// Lane layout: lane == xu (since 192 % 32 == 0), y uniform per warp.
// ---------------------------------------------------------------------------
__global__ __launch_bounds__(192)
void dwgram_k(const float* __restrict__ qkv, const float* __restrict__ dww,
              float* __restrict__ spart)
{
    __shared__ float qs[24][132];
    __shared__ float ks[24][132];

    const int b = blockIdx.z, h = blockIdx.y;
    const int y = blockIdx.x >> 1;
    const int x0 = (blockIdx.x & 1) * 128;
    const int tid = threadIdx.x;
    const int lane = tid & 31;

    for (int u = tid; u < 48 * 32; u += 192) {
        int c = u >> 5;
        int xu = u & 31;              // == lane
        int xg = x0 + xu * 4;
        int ch = (c < 24) ? (h * 24 + c) : (192 + h * 24 + (c - 24));
        const float* in = qkv + ((size_t)(b * QKV_CH + ch) << 16);
        const float* w9 = dww + ch * 9;
        float a0 = 0.f, a1 = 0.f, a2 = 0.f, a3 = 0.f;
#pragma unroll
        for (int dy = -1; dy <= 1; dy++) {
            int yy = y + dy;
            if (yy < 0 || yy > HH - 1) continue;
            const float* r = in + yy * WW;
            float4 m = *(const float4*)(r + xg);
            float left  = __shfl_up_sync(0xffffffffu, m.w, 1);
            float right = __shfl_down_sync(0xffffffffu, m.x, 1);
            if (lane == 0)  left  = (xg > 0)      ? __ldg(r + xg - 1) : 0.f;
            if (lane == 31) right = (xg < WW - 4) ? __ldg(r + xg + 4) : 0.f;
            float w0 = __ldg(w9 + (dy + 1) * 3 + 0);
            float w1 = __ldg(w9 + (dy + 1) * 3 + 1);
            float w2 = __ldg(w9 + (dy + 1) * 3 + 2);
            a0 = fmaf(w0, left, fmaf(w1, m.x, fmaf(w2, m.y, a0)));
            a1 = fmaf(w0, m.x,  fmaf(w1, m.y, fmaf(w2, m.z, a1)));
            a2 = fmaf(w0, m.y,  fmaf(w1, m.z, fmaf(w2, m.w, a2)));
            a3 = fmaf(w0, m.z,  fmaf(w1, m.w, fmaf(w2, right, a3)));
        }
        float* dst = (c < 24) ? &qs[c][xu * 4] : &ks[c - 24][xu * 4];
        *(float4*)dst = make_float4(a0, a1, a2, a3);
    }
    __syncthreads();

    float* out = spart + ((size_t)(b * HEADS + h) * GPB + blockIdx.x) * 624;

    if (tid < 144) {
        int d = (tid / 12) * 2, e = (tid % 12) * 2;
        float a00 = 0, a01 = 0, a10 = 0, a11 = 0;
#pragma unroll 4
        for (int n = 0; n < 128; n += 4) {
            float4 q0 = *(const float4*)&qs[d][n];
            float4 q1 = *(const float4*)&qs[d + 1][n];
            float4 k0 = *(const float4*)&ks[e][n];
            float4 k1 = *(const float4*)&ks[e + 1][n];
            a00 = fmaf(q0.x, k0.x, fmaf(q0.y, k0.y, fmaf(q0.z, k0.z, fmaf(q0.w, k0.w, a00))));
            a01 = fmaf(q0.x, k1.x, fmaf(q0.y, k1.y, fmaf(q0.z, k1.z, fmaf(q0.w, k1.w, a01))));
            a10 = fmaf(q1.x, k0.x, fmaf(q1.y, k0.y, fmaf(q1.z, k0.z, fmaf(q1.w, k0.w, a10))));
            a11 = fmaf(q1.x, k1.x, fmaf(q1.y, k1.y, fmaf(q1.z, k1.z, fmaf(q1.w, k1.w, a11))));
        }
        out[d * 24 + e] = a00;
        out[d * 24 + e + 1] = a01;
        out[(d + 1) * 24 + e] = a10;
        out[(d + 1) * 24 + e + 1] = a11;
    } else if (tid < 168) {
        int d = tid - 144;
        float s = 0;
#pragma unroll 4
        for (int n = 0; n < 128; n += 4) {
            float4 q = *(const float4*)&qs[d][n];
            s = fmaf(q.x, q.x, fmaf(q.y, q.y, fmaf(q.z, q.z, fmaf(q.w, q.w, s))));
        }
        out[576 + d] = s;
    } else {
        int e = tid - 168;
        float s = 0;
#pragma unroll 4
        for (int n = 0; n < 128; n += 4) {
            float4 q = *(const float4*)&ks[e][n];
            s = fmaf(q.x, q.x, fmaf(q.y, q.y, fmaf(q.z, q.z, fmaf(q.w, q.w, s))));
        }
        out[600 + e] = s;
    }
}

// ---------------------------------------------------------------------------
// K3: dwconv for v channels — 4 px/thread, halo via warp shuffle.
// Lane layout: lanes hold consecutive 4-px groups; y uniform per warp.
// ---------------------------------------------------------------------------
__global__ __launch_bounds__(256)
void dwv_k(const float* __restrict__ qkv, const float* __restrict__ dww,
           float* __restrict__ v)
{
    const int b = blockIdx.z, c = blockIdx.y;
    const int tid = threadIdx.x;
    const int lane = tid & 31;
    const int y = blockIdx.x * 4 + (tid >> 6);
    const int x0 = (tid & 63) * 4;
    const int ch = 384 + c;
    const float* in = qkv + ((size_t)(b * QKV_CH + ch) << 16);

    float w9[9];
#pragma unroll
    for (int i = 0; i < 9; i++) w9[i] = __ldg(dww + ch * 9 + i);

    float a0 = 0.f, a1 = 0.f, a2 = 0.f, a3 = 0.f;
#pragma unroll
    for (int dy = -1; dy <= 1; dy++) {
        int yy = y + dy;
        if (yy < 0 || yy > HH - 1) continue;
        const float* r = in + yy * WW;
        float4 m = *(const float4*)(r + x0);
        float left  = __shfl_up_sync(0xffffffffu, m.w, 1);
        float right = __shfl_down_sync(0xffffffffu, m.x, 1);
        if (lane == 0)  left  = (x0 > 0)      ? __ldg(r + x0 - 1) : 0.f;
        if (lane == 31) right = (x0 < WW - 4) ? __ldg(r + x0 + 4) : 0.f;
        const float w0 = w9[(dy + 1) * 3 + 0];
        const float w1 = w9[(dy + 1) * 3 + 1];
        const float w2 = w9[(dy + 1) * 3 + 2];
        a0 = fmaf(w0, left, fmaf(w1, m.x, fmaf(w2, m.y, a0)));
        a1 = fmaf(w0, m.x,  fmaf(w1, m.y, fmaf(w2, m.z, a1)));
        a2 = fmaf(w0, m.y,  fmaf(w1, m.z, fmaf(w2, m.w, a2)));
        a3 = fmaf(w0, m.z,  fmaf(w1, m.w, fmaf(w2, right, a3)));
    }
    *(float4*)&v[((size_t)(b * DIM + c) << 16) + y * WW + x0] =
        make_float4(a0, a1, a2, a3);
}

// ---------------------------------------------------------------------------
// K4+K5 fused: reduce GPB Gram partials, then softmax. Grid 32, block 624.
// ---------------------------------------------------------------------------
__global__ __launch_bounds__(624)
void redsoft_k(const float* __restrict__ spart, const float* __restrict__ temp,
               float* __restrict__ attn)
{
    const int bh = blockIdx.x;
    const int h = bh & 7;
    const int j = threadIdx.x;

    __shared__ float S[624];
    __shared__ float lg[24][24];
    __shared__ float rmax[24], rsum[24];

    {
        const float* p = spart + (size_t)bh * GPB * 624 + j;
        float s = 0.f;
        for (int y = 0; y < GPB; y++) s += p[(size_t)y * 624];
        S[j] = s;
    }
    __syncthreads();

    const int d = j / 24, e = j % 24;
    float l = 0.f;
    if (j < 576) {
        float nq = fmaxf(sqrtf(S[576 + d]), 1e-12f);
        float nk = fmaxf(sqrtf(S[600 + e]), 1e-12f);
        l = S[d * 24 + e] / (nq * nk) * temp[h];
        lg[d][e] = l;
    }
    __syncthreads();
    if (j < 576 && e == 0) {
        float m = -1e30f;
        for (int t = 0; t < 24; t++) m = fmaxf(m, lg[d][t]);
        rmax[d] = m;
    }
    __syncthreads();
    float ex = 0.f;
    if (j < 576) {
        ex = expf(l - rmax[d]);
        lg[d][e] = ex;
    }
    __syncthreads();
    if (j < 576 && e == 0) {
        float s = 0.f;
        for (int t = 0; t < 24; t++) s += lg[d][t];
        rsum[d] = s;
    }
    __syncthreads();
    if (j < 576) attn[bh * 576 + d * 24 + e] = ex / rsum[d];
}

// ---------------------------------------------------------------------------
// K6: M[b] = P * blockdiag(attn[b]) -> extended bf16 rows
// ---------------------------------------------------------------------------
__global__ __launch_bounds__(256)
void buildM_k(const float* __restrict__ attn, const float* __restrict__ P,
              uint32_t* __restrict__ Mext)
{
    const int b = blockIdx.x;
    __shared__ float at[HEADS * 576];
    for (int i = threadIdx.x; i < HEADS * 576; i += 256) at[i] = attn[b * HEADS * 576 + i];
    __syncthreads();

    for (int idx = threadIdx.x; idx < DIM * DIM; idx += 256) {
        int o = idx / DIM, c = idx % DIM;
        int hh = c / 24, e = c % 24;
        float s = 0.f;
#pragma unroll
        for (int d = 0; d < 24; d++)
            s = fmaf(P[o * DIM + hh * 24 + d], at[hh * 576 + d * 24 + e], s);
        uint16_t h, l;
        split_bf16(s, h, l);
        uint16_t* row = (uint16_t*)(Mext + (size_t)b * WCHUNKE) + (size_t)o * KEXT;
        row[c] = h;
        row[192 + c] = l;
        row[384 + c] = h;
    }
}

// ---------------------------------------------------------------------------
// launch
// ---------------------------------------------------------------------------
extern "C" void kernel_launch(void* const* d_in, const int* in_sizes, int n_in,
                              void* d_out, int out_size)
{
    const float* x      = (const float*)d_in[0];
    const float* qkv_w  = (const float*)d_in[1];
    const float* dw_w   = (const float*)d_in[2];
    const float* proj_w = (const float*)d_in[3];
    const float* temp   = (const float*)d_in[4];
    float* out = (float*)d_out;

    float *qkv_s, *v_s, *spart, *attn;
    uint32_t *wext, *Mext;
    cudaGetSymbolAddress((void**)&qkv_s, g_qkv);
    cudaGetSymbolAddress((void**)&v_s,   g_v);
    cudaGetSymbolAddress((void**)&spart, g_spart);
    cudaGetSymbolAddress((void**)&attn,  g_attn);
    cudaGetSymbolAddress((void**)&wext,  g_wext);
    cudaGetSymbolAddress((void**)&Mext,  g_Mext);

    cudaFuncSetAttribute(tgemm_k<3>, cudaFuncAttributeMaxDynamicSharedMemorySize,
                         TGEMM_SMEM);
    cudaFuncSetAttribute(tgemm_k<1>, cudaFuncAttributeMaxDynamicSharedMemorySize,
                         TGEMM_SMEM);

    // K0: weight split/extend
    wprep_k<<<(QKV_CH * DIM + 255) / 256, 256>>>(qkv_w, wext);

    // K1: qkv = W_qkv @ x  (3 m-chunks internal; B tile converted once)
    {
        dim3 grid(HWN / 128, BATCH);
        tgemm_k<3><<<grid, 512, TGEMM_SMEM>>>(wext, x, qkv_s, 0,
                                              (size_t)DIM * HWN, (size_t)QKV_CH * HWN);
    }
    // K2: fused dwconv(q,k) + Gram partials (shuffle halo)
    {
        dim3 grid(GPB, HEADS, BATCH);
        dwgram_k<<<grid, 192>>>(qkv_s, dw_w, spart);
    }
    // K3: dwconv(v), 4 px/thread (shuffle halo)
    {
        dim3 grid(HH / 4, DIM, BATCH);
        dwv_k<<<grid, 256>>>(qkv_s, dw_w, v_s);
    }
    // K4+K5 fused: reduce + softmax
    redsoft_k<<<BATCH * HEADS, 624>>>(spart, temp, attn);
    // K6: M = P * blockdiag(attn) -> extended bf16
    buildM_k<<<BATCH, 256>>>(attn, proj_w, Mext);
    // K7: out = M @ V (NCHUNK=1 instantiation == R11 kernel)
    {
        dim3 grid(HWN / 128, BATCH);
        tgemm_k<1><<<grid, 512, TGEMM_SMEM>>>(Mext, v_s, out, WCHUNKE,
                                              (size_t)DIM * HWN, (size_t)DIM * HWN);
    }
}

// round 15
// speedup vs baseline: 1.5933x; 1.0762x over previous
#include <cuda_runtime.h>
#include <cuda_bf16.h>
#include <math.h>
#include <stdint.h>

// ---------------------------------------------------------------------------
// Problem shapes (fixed)
// ---------------------------------------------------------------------------
#define BATCH 4
#define DIM 192
#define HEADS 8
#define HDIM 24
#define HH 256
#define WW 256
#define HWN 65536
#define QKV_CH 576

#define KEXT 576                     // 3 regions x 192 bf16 slots
#define WROW 288                     // u32 words per extended weight row
#define WCHUNKE (192 * WROW)         // u32 words per 192-row weight chunk

#define GPB 512                      // gram partial blocks per (b,head)
#define RSLICE 16                    // stage-1 reduction slices per (b,head)

// ---------------------------------------------------------------------------
// Scratch (device globals: allocation-free rule)
// ---------------------------------------------------------------------------
__device__ float g_qkv[(size_t)BATCH * QKV_CH * HWN];
__device__ float g_v[(size_t)BATCH * DIM * HWN];
__device__ float g_spart[(size_t)BATCH * HEADS * GPB * 624];
__device__ float g_sred1[BATCH * HEADS * RSLICE * 624];
__device__ float g_attn[BATCH * HEADS * HDIM * HDIM];
__device__ uint32_t g_wext[3 * WCHUNKE];        // qkv weights, 3-term ext rows
__device__ uint32_t g_Mext[BATCH * WCHUNKE];    // proj*blockdiag(attn), ext rows

// ---------------------------------------------------------------------------
// helpers
// ---------------------------------------------------------------------------
__device__ __forceinline__ void split_bf16(float v, uint16_t& h, uint16_t& l) {
    __nv_bfloat16 bh = __float2bfloat16(v);
    float r = v - __bfloat162float(bh);
    __nv_bfloat16 bl = __float2bfloat16(r);
    h = __bfloat16_as_ushort(bh);
    l = __bfloat16_as_ushort(bl);
}

__device__ __forceinline__ void mma16816(float* c, const uint32_t* a, const uint32_t* b) {
    asm volatile(
        "mma.sync.aligned.m16n8k16.row.col.f32.bf16.bf16.f32 "
        "{%0,%1,%2,%3}, {%4,%5,%6,%7}, {%8,%9}, {%0,%1,%2,%3};"
        : "+f"(c[0]), "+f"(c[1]), "+f"(c[2]), "+f"(c[3])
        : "r"(a[0]), "r"(a[1]), "r"(a[2]), "r"(a[3]), "r"(b[0]), "r"(b[1]));
}

// ---------------------------------------------------------------------------
// K0: split qkv weights -> extended bf16 rows [576 rows][576 slots]
// slot k = hi, 192+k = lo, 384+k = hi
// ---------------------------------------------------------------------------
__global__ __launch_bounds__(256)
void wprep_k(const float* __restrict__ w, uint32_t* __restrict__ wext)
{
    int idx = blockIdx.x * 256 + threadIdx.x;
    if (idx >= QKV_CH * DIM) return;
    int r = idx / DIM, k = idx % DIM;
    uint16_t h, l;
    split_bf16(w[idx], h, l);
    uint16_t* row = (uint16_t*)wext + (size_t)r * KEXT;
    row[k] = h;
    row[192 + k] = l;
    row[384 + k] = h;
}

// ---------------------------------------------------------------------------
// tgemm (R6-frozen body, templated chunk count; R11-proven — IMMUTABLE):
// C[m][px] = sum_c W[m][c]*src[c][px], 3-term bf16 split, mma.sync.
// ---------------------------------------------------------------------------
#define AS_STR 20
#define BS_STR 100
#define TGEMM_SMEM ((192 * AS_STR + 2 * 128 * BS_STR) * 4)   // 117760 B

template <int NCHUNK>
__global__ __launch_bounds__(512, 1)
void tgemm_k(const uint32_t* __restrict__ wext, const float* __restrict__ src,
             float* __restrict__ out, size_t wBS, size_t srcBS, size_t outBS)
{
    extern __shared__ uint32_t dsm[];
    uint32_t* As   = dsm;                        // [192][AS_STR]
    uint32_t* Bs_h = dsm + 192 * AS_STR;         // [128 px][BS_STR] (96 used)
    uint32_t* Bs_l = Bs_h + 128 * BS_STR;

    const int tid = threadIdx.x;
    const int wid = tid >> 5;
    const int lane = tid & 31;
    const int g = lane >> 2;
    const int tig = lane & 3;
    const int warpM = wid & 3;
    const int warpN = wid >> 2;

    const int p0 = blockIdx.x * 128;
    const int b = blockIdx.y;

    const uint32_t* wp0 = wext + (size_t)b * wBS;
    const float* sp = src + (size_t)b * srcBS + p0;

    // ---- phase 1: convert pixel tile -> resident Bs_h / Bs_l (once)
#pragma unroll
    for (int pass = 0; pass < 6; pass++) {
        int cpair = pass * 16 + wid;
        const float* r0 = sp + ((size_t)(2 * cpair) << 16);
        const float* r1 = sp + ((size_t)(2 * cpair + 1) << 16);
#pragma unroll
        for (int i = 0; i < 4; i++) {
            int px = lane + 32 * i;
            uint16_t h0, l0, h1, l1;
            split_bf16(__ldg(r0 + px), h0, l0);
            split_bf16(__ldg(r1 + px), h1, l1);
            Bs_h[px * BS_STR + cpair] = (uint32_t)h1 << 16 | h0;
            Bs_l[px * BS_STR + cpair] = (uint32_t)l1 << 16 | l0;
        }
    }

    // A slab loader indices (192 rows x 16 u32 per slab)
    const int aM0 = tid >> 2;
    const int aM1 = 128 + (tid >> 2);
    const int aJ = (tid & 3) * 4;

    for (int chunk = 0; chunk < NCHUNK; chunk++) {
        const uint32_t* wp = wp0 + (size_t)chunk * WCHUNKE;

        float acc[3][4][4];
#pragma unroll
        for (int mt = 0; mt < 3; mt++)
#pragma unroll
            for (int nt = 0; nt < 4; nt++)
#pragma unroll
                for (int i = 0; i < 4; i++) acc[mt][nt][i] = 0.f;

        uint4 apf0, apf1;
        apf0 = *(const uint4*)(wp + (size_t)aM0 * WROW + aJ);
        if (tid < 256) apf1 = *(const uint4*)(wp + (size_t)aM1 * WROW + aJ);
        __syncthreads();   // Bs ready / prior chunk fully done

        for (int it = 0; it < 18; it++) {
            *(uint4*)&As[aM0 * AS_STR + aJ] = apf0;
            if (tid < 256) *(uint4*)&As[aM1 * AS_STR + aJ] = apf1;
            __syncthreads();

            if (it < 17) {
                const uint32_t* wpn = wp + (it + 1) * 16;
                apf0 = *(const uint4*)(wpn + (size_t)aM0 * WROW + aJ);
                if (tid < 256) apf1 = *(const uint4*)(wpn + (size_t)aM1 * WROW + aJ);
            }

            const uint32_t* BsR = (it < 12) ? Bs_h : Bs_l;
            const int bbase = (it % 6) * 16;

#pragma unroll
            for (int ks = 0; ks < 2; ks++) {
                const int kc = ks * 8;
                uint32_t afr[3][4], bfr[4][2];
#pragma unroll
                for (int mt = 0; mt < 3; mt++) {
                    int r0 = warpM * 48 + mt * 16 + g;
                    afr[mt][0] = As[r0 * AS_STR + kc + tig];
                    afr[mt][1] = As[(r0 + 8) * AS_STR + kc + tig];
                    afr[mt][2] = As[r0 * AS_STR + kc + 4 + tig];
                    afr[mt][3] = As[(r0 + 8) * AS_STR + kc + 4 + tig];
                }
#pragma unroll
                for (int nt = 0; nt < 4; nt++) {
                    int n = warpN * 32 + nt * 8 + g;
                    bfr[nt][0] = BsR[n * BS_STR + bbase + kc + tig];
                    bfr[nt][1] = BsR[n * BS_STR + bbase + kc + 4 + tig];
                }
#pragma unroll
                for (int mt = 0; mt < 3; mt++)
#pragma unroll
                    for (int nt = 0; nt < 4; nt++)
                        mma16816(acc[mt][nt], afr[mt], bfr[nt]);
            }
            __syncthreads();
        }

        float* op = out + (size_t)b * outBS + ((size_t)chunk * 192 << 16);
#pragma unroll
        for (int mt = 0; mt < 3; mt++) {
#pragma unroll
            for (int nt = 0; nt < 4; nt++) {
                int row = warpM * 48 + mt * 16 + g;
                int col = p0 + warpN * 32 + nt * 8 + tig * 2;
                *(float2*)&op[((size_t)row << 16) + col] =
                    make_float2(acc[mt][nt][0], acc[mt][nt][1]);
                *(float2*)&op[((size_t)(row + 8) << 16) + col] =
                    make_float2(acc[mt][nt][2], acc[mt][nt][3]);
            }
        }
    }
}

// ---------------------------------------------------------------------------
// K2: fused dwconv (q,k) + Gram partials + norms — R11-proven (no shuffle).
// ---------------------------------------------------------------------------
__global__ __launch_bounds__(192)
void dwgram_k(const float* __restrict__ qkv, const float* __restrict__ dww,
              float* __restrict__ spart)
{
    __shared__ float qs[24][132];
    __shared__ float ks[24][132];

    const int b = blockIdx.z, h = blockIdx.y;
    const int y = blockIdx.x >> 1;
    const int x0 = (blockIdx.x & 1) * 128;
    const int tid = threadIdx.x;

    for (int u = tid; u < 48 * 32; u += 192) {
        int c = u >> 5;
        int xu = u & 31;
        int xg = x0 + xu * 4;
        int ch = (c < 24) ? (h * 24 + c) : (192 + h * 24 + (c - 24));
        const float* in = qkv + ((size_t)(b * QKV_CH + ch) << 16);
        const float* w9 = dww + ch * 9;
        float a0 = 0.f, a1 = 0.f, a2 = 0.f, a3 = 0.f;
#pragma unroll
        for (int dy = -1; dy <= 1; dy++) {
            int yy = y + dy;
            if (yy < 0 || yy > HH - 1) continue;
            const float* r = in + yy * WW;
            float4 m = *(const float4*)(r + xg);
            float left  = (xg > 0)      ? __ldg(r + xg - 1) : 0.f;
            float right = (xg < WW - 4) ? __ldg(r + xg + 4) : 0.f;
            float w0 = __ldg(w9 + (dy + 1) * 3 + 0);
            float w1 = __ldg(w9 + (dy + 1) * 3 + 1);
            float w2 = __ldg(w9 + (dy + 1) * 3 + 2);
            a0 = fmaf(w0, left, fmaf(w1, m.x, fmaf(w2, m.y, a0)));
            a1 = fmaf(w0, m.x,  fmaf(w1, m.y, fmaf(w2, m.z, a1)));
            a2 = fmaf(w0, m.y,  fmaf(w1, m.z, fmaf(w2, m.w, a2)));
            a3 = fmaf(w0, m.z,  fmaf(w1, m.w, fmaf(w2, right, a3)));
        }
        float* dst = (c < 24) ? &qs[c][xu * 4] : &ks[c - 24][xu * 4];
        *(float4*)dst = make_float4(a0, a1, a2, a3);
    }
    __syncthreads();

    float* out = spart + ((size_t)(b * HEADS + h) * GPB + blockIdx.x) * 624;

    if (tid < 144) {
        int d = (tid / 12) * 2, e = (tid % 12) * 2;
        float a00 = 0, a01 = 0, a10 = 0, a11 = 0;
#pragma unroll 4
        for (int n = 0; n < 128; n += 4) {
            float4 q0 = *(const float4*)&qs[d][n];
            float4 q1 = *(const float4*)&qs[d + 1][n];
            float4 k0 = *(const float4*)&ks[e][n];
            float4 k1 = *(const float4*)&ks[e + 1][n];
            a00 = fmaf(q0.x, k0.x, fmaf(q0.y, k0.y, fmaf(q0.z, k0.z, fmaf(q0.w, k0.w, a00))));
            a01 = fmaf(q0.x, k1.x, fmaf(q0.y, k1.y, fmaf(q0.z, k1.z, fmaf(q0.w, k1.w, a01))));
            a10 = fmaf(q1.x, k0.x, fmaf(q1.y, k0.y, fmaf(q1.z, k0.z, fmaf(q1.w, k0.w, a10))));
            a11 = fmaf(q1.x, k1.x, fmaf(q1.y, k1.y, fmaf(q1.z, k1.z, fmaf(q1.w, k1.w, a11))));
        }
        out[d * 24 + e] = a00;
        out[d * 24 + e + 1] = a01;
        out[(d + 1) * 24 + e] = a10;
        out[(d + 1) * 24 + e + 1] = a11;
    } else if (tid < 168) {
        int d = tid - 144;
        float s = 0;
#pragma unroll 4
        for (int n = 0; n < 128; n += 4) {
            float4 q = *(const float4*)&qs[d][n];
            s = fmaf(q.x, q.x, fmaf(q.y, q.y, fmaf(q.z, q.z, fmaf(q.w, q.w, s))));
        }
        out[576 + d] = s;
    } else {
        int e = tid - 168;
        float s = 0;
#pragma unroll 4
        for (int n = 0; n < 128; n += 4) {
            float4 q = *(const float4*)&ks[e][n];
            s = fmaf(q.x, q.x, fmaf(q.y, q.y, fmaf(q.z, q.z, fmaf(q.w, q.w, s))));
        }
        out[600 + e] = s;
    }
}

// ---------------------------------------------------------------------------
// K3: dwconv for v channels — 4 px/thread, float4 I/O (R11-proven, 83.5us).
// ---------------------------------------------------------------------------
__global__ __launch_bounds__(256)
void dwv_k(const float* __restrict__ qkv, const float* __restrict__ dww,
           float* __restrict__ v)
{
    const int b = blockIdx.z, c = blockIdx.y;
    const int tid = threadIdx.x;
    const int y = blockIdx.x * 4 + (tid >> 6);
    const int x0 = (tid & 63) * 4;
    const int ch = 384 + c;
    const float* in = qkv + ((size_t)(b * QKV_CH + ch) << 16);

    float w9[9];
#pragma unroll
    for (int i = 0; i < 9; i++) w9[i] = __ldg(dww + ch * 9 + i);

    float a0 = 0.f, a1 = 0.f, a2 = 0.f, a3 = 0.f;
#pragma unroll
    for (int dy = -1; dy <= 1; dy++) {
        int yy = y + dy;
        if (yy < 0 || yy > HH - 1) continue;
        const float* r = in + yy * WW;
        float4 m = *(const float4*)(r + x0);
        float left  = (x0 > 0)        ? __ldg(r + x0 - 1) : 0.f;
        float right = (x0 < WW - 4)   ? __ldg(r + x0 + 4) : 0.f;
        const float w0 = w9[(dy + 1) * 3 + 0];
        const float w1 = w9[(dy + 1) * 3 + 1];
        const float w2 = w9[(dy + 1) * 3 + 2];
        a0 = fmaf(w0, left, fmaf(w1, m.x, fmaf(w2, m.y, a0)));
        a1 = fmaf(w0, m.x,  fmaf(w1, m.y, fmaf(w2, m.z, a1)));
        a2 = fmaf(w0, m.y,  fmaf(w1, m.z, fmaf(w2, m.w, a2)));
        a3 = fmaf(w0, m.z,  fmaf(w1, m.w, fmaf(w2, right, a3)));
    }
    *(float4*)&v[((size_t)(b * DIM + c) << 16) + y * WW + x0] =
        make_float4(a0, a1, a2, a3);
}

// ---------------------------------------------------------------------------
// K4a: stage-1 reduce — grid (32 bh, RSLICE), block 624.
// Each block sums GPB/RSLICE = 32 partial rows.
// ---------------------------------------------------------------------------
__global__ __launch_bounds__(624)
void rpart_k(const float* __restrict__ spart, float* __restrict__ sred1)
{
    const int bh = blockIdx.x;
    const int sl = blockIdx.y;
    const int j = threadIdx.x;
    const float* p = spart + ((size_t)bh * GPB + sl * (GPB / RSLICE)) * 624 + j;
    float s = 0.f;
    for (int y = 0; y < GPB / RSLICE; y++) s += p[(size_t)y * 624];
    sred1[(bh * RSLICE + sl) * 624 + j] = s;
}

// ---------------------------------------------------------------------------
// K4b+K5: final reduce (RSLICE partials) + softmax. Grid 32, block 624.
// ---------------------------------------------------------------------------
__global__ __launch_bounds__(624)
void redsoft_k(const float* __restrict__ sred1, const float* __restrict__ temp,
               float* __restrict__ attn)
{
    const int bh = blockIdx.x;
    const int h = bh & 7;
    const int j = threadIdx.x;

    __shared__ float S[624];
    __shared__ float lg[24][24];
    __shared__ float rmax[24], rsum[24];

    {
        const float* p = sred1 + (size_t)bh * RSLICE * 624 + j;
        float s = 0.f;
#pragma unroll
        for (int y = 0; y < RSLICE; y++) s += p[(size_t)y * 624];
        S[j] = s;
    }
    __syncthreads();

    const int d = j / 24, e = j % 24;
    float l = 0.f;
    if (j < 576) {
        float nq = fmaxf(sqrtf(S[576 + d]), 1e-12f);
        float nk = fmaxf(sqrtf(S[600 + e]), 1e-12f);
        l = S[d * 24 + e] / (nq * nk) * temp[h];
        lg[d][e] = l;
    }
    __syncthreads();
    if (j < 576 && e == 0) {
        float m = -1e30f;
        for (int t = 0; t < 24; t++) m = fmaxf(m, lg[d][t]);
        rmax[d] = m;
    }
    __syncthreads();
    float ex = 0.f;
    if (j < 576) {
        ex = expf(l - rmax[d]);
        lg[d][e] = ex;
    }
    __syncthreads();
    if (j < 576 && e == 0) {
        float s = 0.f;
        for (int t = 0; t < 24; t++) s += lg[d][t];
        rsum[d] = s;
    }
    __syncthreads();
    if (j < 576) attn[bh * 576 + d * 24 + e] = ex / rsum[d];
}

// ---------------------------------------------------------------------------
// K6: M[b] = P * blockdiag(attn[b]) -> extended bf16 rows.
// Grid (BATCH, 6): each block handles 32 output rows.
// ---------------------------------------------------------------------------
__global__ __launch_bounds__(256)
void buildM_k(const float* __restrict__ attn, const float* __restrict__ P,
              uint32_t* __restrict__ Mext)
{
    const int b = blockIdx.x;
    const int o0 = blockIdx.y * 32;
    __shared__ float at[HEADS * 576];
    for (int i = threadIdx.x; i < HEADS * 576; i += 256) at[i] = attn[b * HEADS * 576 + i];
    __syncthreads();

    for (int idx = threadIdx.x; idx < 32 * DIM; idx += 256) {
        int o = o0 + idx / DIM, c = idx % DIM;
        int hh = c / 24, e = c % 24;
        float s = 0.f;
#pragma unroll
        for (int d = 0; d < 24; d++)
            s = fmaf(P[o * DIM + hh * 24 + d], at[hh * 576 + d * 24 + e], s);
        uint16_t h, l;
        split_bf16(s, h, l);
        uint16_t* row = (uint16_t*)(Mext + (size_t)b * WCHUNKE) + (size_t)o * KEXT;
        row[c] = h;
        row[192 + c] = l;
        row[384 + c] = h;
    }
}

// ---------------------------------------------------------------------------
// launch
// ---------------------------------------------------------------------------
extern "C" void kernel_launch(void* const* d_in, const int* in_sizes, int n_in,
                              void* d_out, int out_size)
{
    const float* x      = (const float*)d_in[0];
    const float* qkv_w  = (const float*)d_in[1];
    const float* dw_w   = (const float*)d_in[2];
    const float* proj_w = (const float*)d_in[3];
    const float* temp   = (const float*)d_in[4];
    float* out = (float*)d_out;

    float *qkv_s, *v_s, *spart, *sred1, *attn;
    uint32_t *wext, *Mext;
    cudaGetSymbolAddress((void**)&qkv_s, g_qkv);
    cudaGetSymbolAddress((void**)&v_s,   g_v);
    cudaGetSymbolAddress((void**)&spart, g_spart);
    cudaGetSymbolAddress((void**)&sred1, g_sred1);
    cudaGetSymbolAddress((void**)&attn,  g_attn);
    cudaGetSymbolAddress((void**)&wext,  g_wext);
    cudaGetSymbolAddress((void**)&Mext,  g_Mext);

    cudaFuncSetAttribute(tgemm_k<3>, cudaFuncAttributeMaxDynamicSharedMemorySize,
                         TGEMM_SMEM);
    cudaFuncSetAttribute(tgemm_k<1>, cudaFuncAttributeMaxDynamicSharedMemorySize,
                         TGEMM_SMEM);

    // K0: weight split/extend
    wprep_k<<<(QKV_CH * DIM + 255) / 256, 256>>>(qkv_w, wext);

    // K1: qkv = W_qkv @ x  (3 m-chunks internal; B tile converted once)
    {
        dim3 grid(HWN / 128, BATCH);
        tgemm_k<3><<<grid, 512, TGEMM_SMEM>>>(wext, x, qkv_s, 0,
                                              (size_t)DIM * HWN, (size_t)QKV_CH * HWN);
    }
    // K2: fused dwconv(q,k) + Gram partials
    {
        dim3 grid(GPB, HEADS, BATCH);
        dwgram_k<<<grid, 192>>>(qkv_s, dw_w, spart);
    }
    // K3: dwconv(v), 4 px/thread
    {
        dim3 grid(HH / 4, DIM, BATCH);
        dwv_k<<<grid, 256>>>(qkv_s, dw_w, v_s);
    }
    // K4a: stage-1 Gram reduction (parallel over slices)
    {
        dim3 grid(BATCH * HEADS, RSLICE);
        rpart_k<<<grid, 624>>>(spart, sred1);
    }
    // K4b+K5: final reduce + softmax
    redsoft_k<<<BATCH * HEADS, 624>>>(sred1, temp, attn);
    // K6: M = P * blockdiag(attn) -> extended bf16 (6 row-slices per batch)
    {
        dim3 grid(BATCH, 6);
        buildM_k<<<grid, 256>>>(attn, proj_w, Mext);
    }
    // K7: out = M @ V (NCHUNK=1 instantiation == R11 kernel)
    {
        dim3 grid(HWN / 128, BATCH);
        tgemm_k<1><<<grid, 512, TGEMM_SMEM>>>(Mext, v_s, out, WCHUNKE,
                                              (size_t)DIM * HWN, (size_t)DIM * HWN);
    }
}